// round 16
// baseline (speedup 1.0000x reference)
#include <cuda_runtime.h>

// Grid: 128^3 cells, cell = (bin+64), idx = x + 128*y + 16384*z
// Each cell: float4 {sum_x, sum_y, sum_z, count}
#define D    128
#define D3   (128*128*128)
#define OFF  64
#define NMAX 200704

__device__ float4 g_gridA[D3];     // scatter ping
__device__ float4 g_gridB[D3];     // scatter pong
__device__ float4 g_grid1[D3];     // yz-smoothed field / gather source
__device__ float4 g_Xbuf4[2][(NMAX * 3) / 4];   // float4-aligned point buffers
__device__ int    g_actA[16 * 128];   // activity flag per (ytile=y>>3, z)
__device__ int    g_actB[16 * 128];
__device__ unsigned g_maxd2_bits;
__device__ int g_done;

// ---------------------------------------------------------------- helpers
__device__ __forceinline__ int bin_of(float v) {
    // match jnp: (X / 0.1f).astype(int32) == IEEE RN divide, trunc toward zero
    int b = (int)__fdiv_rn(v, 0.1f);
    b += OFF;
    return min(max(b, 0), D - 1);
}

__device__ __forceinline__ void red4(float4* p, float x, float y, float z, float w) {
    asm volatile("red.global.add.v4.f32 [%0], {%1, %2, %3, %4};"
                 :: "l"(p), "f"(x), "f"(y), "f"(z), "f"(w) : "memory");
}

// (a+e) + 2(b+d) + 3c, componentwise
__device__ __forceinline__ float4 w5(float4 a, float4 b, float4 c, float4 d, float4 e) {
    float4 o;
    o.x = (a.x + e.x) + 2.f * (b.x + d.x) + 3.f * c.x;
    o.y = (a.y + e.y) + 2.f * (b.y + d.y) + 3.f * c.y;
    o.z = (a.z + e.z) + 2.f * (b.z + d.z) + 3.f * c.z;
    o.w = (a.w + e.w) + 2.f * (b.w + d.w) + 3.f * c.w;
    return o;
}

// scatter one point into grid+flags
__device__ __forceinline__ void scat1(float4* grid, int* act,
                                      float px, float py, float pz) {
    int yb = bin_of(py), zb = bin_of(pz);
    int cell = bin_of(px) + (yb << 7) + (zb << 14);
    act[((yb >> 3) << 7) + zb] = 1;
    red4(&grid[cell], px, py, pz, 1.0f);
}

// ---------------------------------------------------------------- initial scatter (step 0 only)
// 4 consecutive points per thread, X read as 3 x LDG.128.
__global__ __launch_bounds__(256) void scatter0_kernel(const float* __restrict__ X, int n) {
    int i = blockIdx.x * blockDim.x + threadIdx.x;
    int p0 = i * 4;
    if (p0 + 3 < n) {
        const float4* __restrict__ X4 = (const float4*)X;
        float4 f0 = X4[3 * i + 0];
        float4 f1 = X4[3 * i + 1];
        float4 f2 = X4[3 * i + 2];
        scat1(g_gridA, g_actA, f0.x, f0.y, f0.z);
        scat1(g_gridA, g_actA, f0.w, f1.x, f1.y);
        scat1(g_gridA, g_actA, f1.z, f1.w, f2.x);
        scat1(g_gridA, g_actA, f2.y, f2.z, f2.w);
    } else {
        for (int p = p0; p < n; p++)
            scat1(g_gridA, g_actA, X[3 * p], X[3 * p + 1], X[3 * p + 2]);
    }
}

// ---------------------------------------------------------------- y+z separable conv (NO smem, NO syncs)
// weights [1,2,3,2,1] in y and z; x-filter applied at gather. 512 blocks x
// 512 threads (full x-line, 4 output y-rows, zseg of 8) -> 2 blocks/SM,
// finer tail balance. Each thread loads its own 5 y-rows per slice (L1
// reuse), z via 5-deep register ring rotated by 5x unroll.

__device__ __forceinline__ float4 ysum(const float4* __restrict__ src,
                                       int xo, const int* yo, int zc) {
    const float4* p = src + xo + ((min(max(zc, 0), D - 1)) << 14);
    return w5(p[yo[0]], p[yo[1]], p[yo[2]], p[yo[3]], p[yo[4]]);
}

__global__ __launch_bounds__(512) void convyz_kernel(int sel, int first) {
    if (blockIdx.x == 0 && threadIdx.x == 0) {
        // fold convergence check: uses previous step's max displacement^2
        if (first) g_done = 0;
        else if (__uint_as_float(g_maxd2_bits) <= 1e-6f) g_done = 1;
        g_maxd2_bits = 0u;
    }

    const float4* __restrict__ src = sel ? g_gridB : g_gridA;
    const int* __restrict__ act = sel ? g_actB : g_actA;

    int x = threadIdx.x & 127;
    int lane = threadIdx.x & 31;
    int r = threadIdx.x >> 7;            // 0..3
    int yq = blockIdx.x & 31;            // 32 y-quads of 4 rows
    int z0 = (blockIdx.x >> 5) << 3;     // 16 z-segments of 8 slices
    int y0 = yq << 2;

    // per-warp activity ballot (flags are 8-row granularity)
    int f = (lane < 8) ? act[((y0 >> 3) << 7) + z0 + lane] : 0;
    unsigned need = __ballot_sync(0xffffffffu, f != 0) & 0xffu;
    if (!need) return;
    int zlo = z0 + __ffs(need) - 1;
    int zhi = z0 + 31 - __clz(need);
    int nsl = zhi - zlo + 5;             // raw slices zlo-2 .. zhi+2

    int yo[5];
#pragma unroll
    for (int j = 0; j < 5; j++)
        yo[j] = (min(max(y0 + r - 2 + j, 0), D - 1)) << 7;

    float4* __restrict__ outp = g_grid1 + x + ((y0 + r) << 7);

    float4 q0, q1, q2, q3, q4;           // z ring of y-smoothed slices
    q0 = q1 = q2 = q3 = q4 = make_float4(0.f, 0.f, 0.f, 0.f);

    int zi = 0;
    while (true) {
        q0 = ysum(src, x, yo, zlo - 2 + zi);
        if (zi >= 4) outp[(zlo - 4 + zi) << 14] = w5(q1, q2, q3, q4, q0);
        if (++zi >= nsl) break;
        q1 = ysum(src, x, yo, zlo - 2 + zi);
        if (zi >= 4) outp[(zlo - 4 + zi) << 14] = w5(q2, q3, q4, q0, q1);
        if (++zi >= nsl) break;
        q2 = ysum(src, x, yo, zlo - 2 + zi);
        if (zi >= 4) outp[(zlo - 4 + zi) << 14] = w5(q3, q4, q0, q1, q2);
        if (++zi >= nsl) break;
        q3 = ysum(src, x, yo, zlo - 2 + zi);
        if (zi >= 4) outp[(zlo - 4 + zi) << 14] = w5(q4, q0, q1, q2, q3);
        if (++zi >= nsl) break;
        q4 = ysum(src, x, yo, zlo - 2 + zi);
        if (zi >= 4) outp[(zlo - 4 + zi) << 14] = w5(q0, q1, q2, q3, q4);
        if (++zi >= nsl) break;
    }
}

// ---------------------------------------------------------------- fused gather + scatter(next)
// 4 consecutive points per thread; X as 3 LDG.128, Y as 3 STG.128.
// Gather applies the x-filter (5 taps, L2-hot).
__device__ __forceinline__ float gs1(float px, float py, float pz,
                                     float& nx, float& ny, float& nz,
                                     float4* gOld, float4* gNew,
                                     int* actOld, int* actNew,
                                     int done, int doScatter) {
    int xb = bin_of(px), yb = bin_of(py), zb = bin_of(pz);
    int rowbase = (yb << 7) + (zb << 14);
    const float4* __restrict__ g = g_grid1 + rowbase;
    float4 t = w5(g[max(xb - 2, 0)], g[max(xb - 1, 0)], g[xb],
                  g[min(xb + 1, D - 1)], g[min(xb + 2, D - 1)]);
    // undo this step's scatter: keeps grids & flags all-zero at boundaries
    gOld[xb + rowbase] = make_float4(0.f, 0.f, 0.f, 0.f);
    actOld[((yb >> 3) << 7) + zb] = 0;
    nx = __fdiv_rn(t.x, t.w);
    ny = __fdiv_rn(t.y, t.w);
    nz = __fdiv_rn(t.z, t.w);
    if (done) { nx = px; ny = py; nz = pz; }
    float dx = nx - px, dy = ny - py, dz = nz - pz;
    if (doScatter) {
        int nyb = bin_of(ny), nzb = bin_of(nz);
        int ncell = bin_of(nx) + (nyb << 7) + (nzb << 14);
        actNew[((nyb >> 3) << 7) + nzb] = 1;
        red4(&gNew[ncell], nx, ny, nz, 1.0f);
    }
    return dx * dx + dy * dy + dz * dz;
}

__global__ __launch_bounds__(256) void fused_gs_kernel(
        const float* __restrict__ Xext, int srcSel,
        float* __restrict__ Oext, int dstSel,
        int gsel, int doScatter, int n) {
    __shared__ float s_max[8];
    const float4* __restrict__ X4 =
        (srcSel < 0) ? (const float4*)Xext : g_Xbuf4[srcSel];
    float4* __restrict__ Y4 = (dstSel < 0) ? (float4*)Oext : g_Xbuf4[dstSel];
    float4* gOld = gsel ? g_gridB : g_gridA;   // consumed this step -> zero
    float4* gNew = gsel ? g_gridA : g_gridB;   // next step's scatter target
    int* actOld = gsel ? g_actB : g_actA;
    int* actNew = gsel ? g_actA : g_actB;
    int done = g_done;

    int i = blockIdx.x * blockDim.x + threadIdx.x;
    int p0 = i * 4;
    float d2 = 0.f;
    if (p0 + 3 < n) {
        float4 f0 = X4[3 * i + 0];
        float4 f1 = X4[3 * i + 1];
        float4 f2 = X4[3 * i + 2];
        float n0x, n0y, n0z, n1x, n1y, n1z, n2x, n2y, n2z, n3x, n3y, n3z;
        d2 = fmaxf(d2, gs1(f0.x, f0.y, f0.z, n0x, n0y, n0z,
                           gOld, gNew, actOld, actNew, done, doScatter));
        d2 = fmaxf(d2, gs1(f0.w, f1.x, f1.y, n1x, n1y, n1z,
                           gOld, gNew, actOld, actNew, done, doScatter));
        d2 = fmaxf(d2, gs1(f1.z, f1.w, f2.x, n2x, n2y, n2z,
                           gOld, gNew, actOld, actNew, done, doScatter));
        d2 = fmaxf(d2, gs1(f2.y, f2.z, f2.w, n3x, n3y, n3z,
                           gOld, gNew, actOld, actNew, done, doScatter));
        Y4[3 * i + 0] = make_float4(n0x, n0y, n0z, n1x);
        Y4[3 * i + 1] = make_float4(n1y, n1z, n2x, n2y);
        Y4[3 * i + 2] = make_float4(n2z, n3x, n3y, n3z);
    } else {
        const float* X = (const float*)X4;
        float* Y = (float*)Y4;
        for (int p = p0; p < n; p++) {
            float nx, ny, nz;
            d2 = fmaxf(d2, gs1(X[3 * p], X[3 * p + 1], X[3 * p + 2],
                               nx, ny, nz, gOld, gNew, actOld, actNew,
                               done, doScatter));
            Y[3 * p + 0] = nx;
            Y[3 * p + 1] = ny;
            Y[3 * p + 2] = nz;
        }
    }
#pragma unroll
    for (int o = 16; o > 0; o >>= 1)
        d2 = fmaxf(d2, __shfl_xor_sync(0xFFFFFFFFu, d2, o));
    int wid = threadIdx.x >> 5;
    if ((threadIdx.x & 31) == 0) s_max[wid] = d2;
    __syncthreads();
    if (threadIdx.x < 8) {
        float v = s_max[threadIdx.x];
#pragma unroll
        for (int o = 4; o > 0; o >>= 1)
            v = fmaxf(v, __shfl_xor_sync(0xFFu, v, o));
        if (threadIdx.x == 0)
            atomicMax(&g_maxd2_bits, __float_as_uint(v));
    }
}

// ---------------------------------------------------------------- launch
extern "C" void kernel_launch(void* const* d_in, const int* in_sizes, int n_in,
                              void* d_out, int out_size) {
    const float* Xin = (const float*)d_in[0];
    float* Out = (float*)d_out;
    int n = in_sizes[0] / 3;

    int nq = (n + 3) / 4;                // 4 points per thread
    int pblocks = (nq + 255) / 256;
    int srcSel[5] = {-1, 0, 1, 0, 1};
    int dstSel[5] = { 0, 1, 0, 1, -1};

    scatter0_kernel<<<pblocks, 256>>>(Xin, n);
    for (int s = 0; s < 5; s++) {
        int gsel = s & 1;
        convyz_kernel<<<512, 512>>>(gsel, s == 0);
        fused_gs_kernel<<<pblocks, 256>>>(Xin, srcSel[s], Out, dstSel[s],
                                          gsel, s < 4, n);
    }
}

// round 17
// speedup vs baseline: 1.3809x; 1.3809x over previous
#include <cuda_runtime.h>

// Grid: 128^3 cells, cell = (bin+64), idx = x + 128*y + 16384*z
// Each cell: float4 {sum_x, sum_y, sum_z, count}
#define D    128
#define D3   (128*128*128)
#define OFF  64
#define NMAX 200704

__device__ float4 g_gridA[D3];     // scatter ping
__device__ float4 g_gridB[D3];     // scatter pong
__device__ float4 g_grid1[D3];     // yz-smoothed field / gather source
__device__ float  g_Xbuf[2][NMAX * 3];
__device__ int    g_actA[128 * 128];  // activity flag per (y, z) row
__device__ int    g_actB[128 * 128];
__device__ unsigned g_maxd2_bits;
__device__ int g_done;

// ---------------------------------------------------------------- helpers
__device__ __forceinline__ int bin_of(float v) {
    // match jnp: (X / 0.1f).astype(int32) == IEEE RN divide, trunc toward zero
    int b = (int)__fdiv_rn(v, 0.1f);
    b += OFF;
    return min(max(b, 0), D - 1);
}

__device__ __forceinline__ void red4(float4* p, float x, float y, float z, float w) {
    asm volatile("red.global.add.v4.f32 [%0], {%1, %2, %3, %4};"
                 :: "l"(p), "f"(x), "f"(y), "f"(z), "f"(w) : "memory");
}

// (a+e) + 2(b+d) + 3c, componentwise
__device__ __forceinline__ float4 w5(float4 a, float4 b, float4 c, float4 d, float4 e) {
    float4 o;
    o.x = (a.x + e.x) + 2.f * (b.x + d.x) + 3.f * c.x;
    o.y = (a.y + e.y) + 2.f * (b.y + d.y) + 3.f * c.y;
    o.z = (a.z + e.z) + 2.f * (b.z + d.z) + 3.f * c.z;
    o.w = (a.w + e.w) + 2.f * (b.w + d.w) + 3.f * c.w;
    return o;
}

// ---------------------------------------------------------------- initial scatter (step 0 only)
__global__ __launch_bounds__(1024) void scatter0_kernel(const float* __restrict__ X, int n) {
    int i = blockIdx.x * blockDim.x + threadIdx.x;
    if (i >= n) return;
    float x = X[3 * i + 0];
    float y = X[3 * i + 1];
    float z = X[3 * i + 2];
    int yb = bin_of(y), zb = bin_of(z);
    int cell = bin_of(x) + (yb << 7) + (zb << 14);
    g_actA[(yb << 7) + zb] = 1;
    red4(&g_gridA[cell], x, y, z, 1.0f);
}

// ---------------------------------------------------------------- y+z separable conv (NO smem, NO syncs)
// weights [1,2,3,2,1] in y and z; x-filter applied at gather time.
// Block: full x-line (128) x 8 y-rows, zseg of 8; 256 blocks x 1024 threads.
// Each WARP serves one y-row (32 x-lanes, fixed r) -> activity is balloted
// per ROW at (y,z) granularity: empty rows exit instantly, occupied rows get
// a minimal z-window. Threads load their own 5 y-rows per slice (L1 reuse),
// z via 5-deep register ring rotated by 5x unroll.

__device__ __forceinline__ float4 ysum(const float4* __restrict__ src,
                                       int xo, const int* yo, int zc) {
    const float4* p = src + xo + ((min(max(zc, 0), D - 1)) << 14);
    return w5(p[yo[0]], p[yo[1]], p[yo[2]], p[yo[3]], p[yo[4]]);
}

__global__ __launch_bounds__(1024) void convyz_kernel(int sel, int first) {
    if (blockIdx.x == 0 && threadIdx.x == 0) {
        // fold convergence check: uses previous step's max displacement^2
        if (first) g_done = 0;
        else if (__uint_as_float(g_maxd2_bits) <= 1e-6f) g_done = 1;
        g_maxd2_bits = 0u;
    }

    const float4* __restrict__ src = sel ? g_gridB : g_gridA;
    const int* __restrict__ act = sel ? g_actB : g_actA;

    int x = threadIdx.x & 127;
    int lane = threadIdx.x & 31;
    int r = threadIdx.x >> 7;            // 0..7  (warp-uniform)
    int yt = blockIdx.x & 15;            // 16 y-tiles of 8 rows
    int z0 = (blockIdx.x >> 4) << 3;     // 16 z-segments of 8 slices
    int y = (yt << 3) + r;               // this warp's output row

    // per-ROW activity ballot (warp-uniform: all lanes share y)
    int f = (lane < 8) ? act[(y << 7) + z0 + lane] : 0;
    unsigned need = __ballot_sync(0xffffffffu, f != 0) & 0xffu;
    if (!need) return;
    int zlo = z0 + __ffs(need) - 1;
    int zhi = z0 + 31 - __clz(need);
    int nsl = zhi - zlo + 5;             // raw slices zlo-2 .. zhi+2

    int yo[5];
#pragma unroll
    for (int j = 0; j < 5; j++)
        yo[j] = (min(max(y - 2 + j, 0), D - 1)) << 7;

    float4* __restrict__ outp = g_grid1 + x + (y << 7);

    float4 q0, q1, q2, q3, q4;           // z ring of y-smoothed slices
    q0 = q1 = q2 = q3 = q4 = make_float4(0.f, 0.f, 0.f, 0.f);

    int zi = 0;
    while (true) {
        q0 = ysum(src, x, yo, zlo - 2 + zi);
        if (zi >= 4) outp[(zlo - 4 + zi) << 14] = w5(q1, q2, q3, q4, q0);
        if (++zi >= nsl) break;
        q1 = ysum(src, x, yo, zlo - 2 + zi);
        if (zi >= 4) outp[(zlo - 4 + zi) << 14] = w5(q2, q3, q4, q0, q1);
        if (++zi >= nsl) break;
        q2 = ysum(src, x, yo, zlo - 2 + zi);
        if (zi >= 4) outp[(zlo - 4 + zi) << 14] = w5(q3, q4, q0, q1, q2);
        if (++zi >= nsl) break;
        q3 = ysum(src, x, yo, zlo - 2 + zi);
        if (zi >= 4) outp[(zlo - 4 + zi) << 14] = w5(q4, q0, q1, q2, q3);
        if (++zi >= nsl) break;
        q4 = ysum(src, x, yo, zlo - 2 + zi);
        if (zi >= 4) outp[(zlo - 4 + zi) << 14] = w5(q0, q1, q2, q3, q4);
        if (++zi >= nsl) break;
    }
}

// ---------------------------------------------------------------- fused gather + scatter(next)
// Gather applies the x-filter: 5 taps around the point's cell (L2-hot).
// 1 point per thread (max warp-level parallelism — R15-proven).
__global__ __launch_bounds__(1024) void fused_gs_kernel(
        const float* __restrict__ Xext, int srcSel,
        float* __restrict__ Oext, int dstSel,
        int gsel, int doScatter, int n) {
    __shared__ float s_max[32];
    const float* X = (srcSel < 0) ? Xext : g_Xbuf[srcSel];
    float* Y = (dstSel < 0) ? Oext : g_Xbuf[dstSel];
    float4* gOld = gsel ? g_gridB : g_gridA;   // consumed this step -> zero
    float4* gNew = gsel ? g_gridA : g_gridB;   // next step's scatter target
    int* actOld = gsel ? g_actB : g_actA;
    int* actNew = gsel ? g_actA : g_actB;

    int i = blockIdx.x * blockDim.x + threadIdx.x;
    float d2 = 0.f;
    if (i < n) {
        float x = X[3 * i + 0];
        float y = X[3 * i + 1];
        float z = X[3 * i + 2];
        int xb = bin_of(x), yb = bin_of(y), zb = bin_of(z);
        int rowbase = (yb << 7) + (zb << 14);
        int cell = xb + rowbase;
        // x-filter from the yz-smoothed field (same cache line mostly)
        const float4* __restrict__ g = g_grid1 + rowbase;
        float4 t = w5(g[max(xb - 2, 0)], g[max(xb - 1, 0)], g[xb],
                      g[min(xb + 1, D - 1)], g[min(xb + 2, D - 1)]);
        // undo this step's scatter: keeps grids & flags all-zero at boundaries
        gOld[cell] = make_float4(0.f, 0.f, 0.f, 0.f);
        actOld[(yb << 7) + zb] = 0;
        float nx = __fdiv_rn(t.x, t.w);
        float ny = __fdiv_rn(t.y, t.w);
        float nz = __fdiv_rn(t.z, t.w);
        if (g_done) { nx = x; ny = y; nz = z; }
        Y[3 * i + 0] = nx;
        Y[3 * i + 1] = ny;
        Y[3 * i + 2] = nz;
        float dx = nx - x, dy = ny - y, dz = nz - z;
        d2 = dx * dx + dy * dy + dz * dz;
        if (doScatter) {
            int nyb = bin_of(ny), nzb = bin_of(nz);
            int ncell = bin_of(nx) + (nyb << 7) + (nzb << 14);
            actNew[(nyb << 7) + nzb] = 1;
            red4(&gNew[ncell], nx, ny, nz, 1.0f);
        }
    }
#pragma unroll
    for (int o = 16; o > 0; o >>= 1)
        d2 = fmaxf(d2, __shfl_xor_sync(0xFFFFFFFFu, d2, o));
    int wid = threadIdx.x >> 5;
    if ((threadIdx.x & 31) == 0) s_max[wid] = d2;
    __syncthreads();
    if (threadIdx.x < 32) {
        float v = s_max[threadIdx.x];
#pragma unroll
        for (int o = 16; o > 0; o >>= 1)
            v = fmaxf(v, __shfl_xor_sync(0xFFFFFFFFu, v, o));
        if (threadIdx.x == 0)
            atomicMax(&g_maxd2_bits, __float_as_uint(v));
    }
}

// ---------------------------------------------------------------- launch
extern "C" void kernel_launch(void* const* d_in, const int* in_sizes, int n_in,
                              void* d_out, int out_size) {
    const float* Xin = (const float*)d_in[0];
    float* Out = (float*)d_out;
    int n = in_sizes[0] / 3;

    int pblocks = (n + 1023) / 1024;
    int srcSel[5] = {-1, 0, 1, 0, 1};
    int dstSel[5] = { 0, 1, 0, 1, -1};

    scatter0_kernel<<<pblocks, 1024>>>(Xin, n);
    for (int s = 0; s < 5; s++) {
        int gsel = s & 1;
        convyz_kernel<<<256, 1024>>>(gsel, s == 0);
        fused_gs_kernel<<<pblocks, 1024>>>(Xin, srcSel[s], Out, dstSel[s],
                                           gsel, s < 4, n);
    }
}